// round 1
// baseline (speedup 1.0000x reference)
#include <cuda_runtime.h>
#include <math.h>

#define Nn 20000
#define Ee 320000
#define EP (Ee + Nn)
#define Gg 64
#define IND 23
#define EDD 6
#define Hh 256
#define NEGS 0.2f
#define EPSL 1e-5f

// ---------------- scratch (device globals; no allocation allowed) ----------------
__device__ __align__(16) float g_hl[Nn * Hh];
__device__ __align__(16) float g_hr[Nn * Hh];
__device__ __align__(16) float g_h[Nn * Hh];
__device__ float g_loop_attr[Nn * EDD];
__device__ int g_deg[Nn];
__device__ int g_rowptr[Nn + 1];
__device__ int g_fill[Nn];
__device__ int g_eid[EP];
__device__ int g_gcnt[Gg];
__device__ int g_gstart[Gg + 1];
__device__ __align__(16) float g_pool[Gg * Hh];

// ---------------- setup kernels ----------------
__global__ void k_init() {
    int i = blockIdx.x * blockDim.x + threadIdx.x;
    int stride = gridDim.x * blockDim.x;
    for (int n = i; n < Nn; n += stride) { g_deg[n] = 0; g_fill[n] = 0; }
    for (int n = i; n < Nn * EDD; n += stride) g_loop_attr[n] = 0.f;
    if (i < Gg) g_gcnt[i] = 0;
}

__global__ void k_hist(const int* __restrict__ dst, const float* __restrict__ eattr) {
    int e = blockIdx.x * blockDim.x + threadIdx.x;
    if (e >= Ee) return;
    int d = dst[e];
    atomicAdd(&g_deg[d], 1);
#pragma unroll
    for (int t = 0; t < EDD; t++) atomicAdd(&g_loop_attr[d * EDD + t], eattr[e * EDD + t]);
}

__global__ void k_nodeprep(const int* __restrict__ batch) {
    int n = blockIdx.x * blockDim.x + threadIdx.x;
    if (n >= Nn) return;
    int dg = g_deg[n];
    float inv = 1.f / (float)(dg > 1 ? dg : 1);
#pragma unroll
    for (int t = 0; t < EDD; t++) g_loop_attr[n * EDD + t] *= inv;
    atomicAdd(&g_gcnt[batch[n]], 1);
}

__global__ void k_scan() {
    __shared__ int sm[1024];
    int t = threadIdx.x;
    int running = 0;
    for (int base = 0; base < Nn; base += 1024) {
        int idx = base + t;
        int v = (idx < Nn) ? (g_deg[idx] + 1) : 0;
        sm[t] = v;
        __syncthreads();
        for (int d = 1; d < 1024; d <<= 1) {
            int tmp = (t >= d) ? sm[t - d] : 0;
            __syncthreads();
            sm[t] += tmp;
            __syncthreads();
        }
        if (idx < Nn) g_rowptr[idx] = running + sm[t] - v;  // exclusive
        running += sm[1023];
        __syncthreads();
    }
    if (t == 0) g_rowptr[Nn] = running;
}

__global__ void k_gstart() {
    if (threadIdx.x == 0 && blockIdx.x == 0) {
        int acc = 0;
        for (int g = 0; g < Gg; g++) { g_gstart[g] = acc; acc += g_gcnt[g]; }
        g_gstart[Gg] = acc;
    }
}

__global__ void k_scatter(const int* __restrict__ dst) {
    int e = blockIdx.x * blockDim.x + threadIdx.x;
    if (e >= EP) return;
    int d = (e < Ee) ? dst[e] : (e - Ee);
    int slot = g_rowptr[d] + atomicAdd(&g_fill[d], 1);
    g_eid[slot] = e;
}

// ---------------- GEMM: [hl|hr] = A @ [Wl|Wr] + [bl|br] ----------------
// BM=128, BN=128, BK=16, 256 threads, 8x8 thread tile
__global__ __launch_bounds__(256) void k_gemm(const float* __restrict__ A, int K,
                                              const float* __restrict__ Wl,
                                              const float* __restrict__ Wr,
                                              const float* __restrict__ bl,
                                              const float* __restrict__ br) {
    __shared__ float As[16][128];
    __shared__ float Bs[16][128];
    int t = threadIdx.x;
    int m0 = blockIdx.x * 128;
    int halfsel = blockIdx.y >> 1;
    int cb = (blockIdx.y & 1) * 128;
    const float* W = halfsel ? Wr : Wl;
    const float* bias = halfsel ? br : bl;
    float* outp = halfsel ? g_hr : g_hl;
    int ty = t >> 4, tx = t & 15;
    float acc[8][8];
#pragma unroll
    for (int i = 0; i < 8; i++)
#pragma unroll
        for (int j = 0; j < 8; j++) acc[i][j] = 0.f;

    for (int k0 = 0; k0 < K; k0 += 16) {
#pragma unroll
        for (int i = 0; i < 8; i++) {
            int lin = t + 256 * i;
            int k = lin & 15, m = lin >> 4;
            int row = m0 + m, kk = k0 + k;
            As[k][m] = (row < Nn && kk < K) ? A[(size_t)row * K + kk] : 0.f;
        }
#pragma unroll
        for (int i = 0; i < 8; i++) {
            int lin = t + 256 * i;
            int nn = lin & 127, k = lin >> 7;
            int kk = k0 + k;
            Bs[k][nn] = (kk < K) ? W[(size_t)kk * Hh + cb + nn] : 0.f;
        }
        __syncthreads();
#pragma unroll
        for (int k = 0; k < 16; k++) {
            float a[8], b[8];
#pragma unroll
            for (int i = 0; i < 8; i++) { a[i] = As[k][ty * 8 + i]; b[i] = Bs[k][tx * 8 + i]; }
#pragma unroll
            for (int i = 0; i < 8; i++)
#pragma unroll
                for (int j = 0; j < 8; j++) acc[i][j] = fmaf(a[i], b[j], acc[i][j]);
        }
        __syncthreads();
    }
#pragma unroll
    for (int i = 0; i < 8; i++) {
        int row = m0 + ty * 8 + i;
        if (row >= Nn) continue;
#pragma unroll
        for (int j = 0; j < 8; j++) {
            int col = cb + tx * 8 + j;
            outp[(size_t)row * Hh + col] = acc[i][j] + bias[col];
        }
    }
}

// ---------------- Fused edge kernel: one warp per node ----------------
// online softmax over in-edges + aggregation + bias + layernorm + relu
__global__ __launch_bounds__(256) void k_edge(const int* __restrict__ srcArr,
                                              const float* __restrict__ eattr,
                                              const float* __restrict__ We,
                                              const float* __restrict__ att,
                                              const float* __restrict__ bias,
                                              const float* __restrict__ lnw,
                                              const float* __restrict__ lnb) {
    int warp = threadIdx.x >> 5, lane = threadIdx.x & 31;
    int n = blockIdx.x * 8 + warp;
    if (n >= Nn) return;

    const float4* hlv = (const float4*)g_hl;
    const float4* hrv = (const float4*)g_hr;

    float4 h0 = hrv[n * 64 + lane], h1 = hrv[n * 64 + 32 + lane];
    float hv[8] = {h0.x, h0.y, h0.z, h0.w, h1.x, h1.y, h1.z, h1.w};
    const float4* attv = (const float4*)att;
    float4 a0 = attv[lane], a1 = attv[32 + lane];
    float av[8] = {a0.x, a0.y, a0.z, a0.w, a1.x, a1.y, a1.z, a1.w};

    float wef[6][8];
    const float4* Wev = (const float4*)We;
#pragma unroll
    for (int d = 0; d < 6; d++) {
        float4 w0 = Wev[d * 64 + lane], w1 = Wev[d * 64 + 32 + lane];
        wef[d][0] = w0.x; wef[d][1] = w0.y; wef[d][2] = w0.z; wef[d][3] = w0.w;
        wef[d][4] = w1.x; wef[d][5] = w1.y; wef[d][6] = w1.z; wef[d][7] = w1.w;
    }

    int r0 = g_rowptr[n], r1 = g_rowptr[n + 1];
    float mx = -3.4e38f;
    float ssum = 0.f;
    float acc[8] = {0.f, 0.f, 0.f, 0.f, 0.f, 0.f, 0.f, 0.f};

    for (int s = r0; s < r1; s++) {
        int eid = g_eid[s];
        int u;
        const float* ar;
        if (eid < Ee) { u = srcArr[eid]; ar = eattr + (size_t)eid * EDD; }
        else          { u = eid - Ee;    ar = g_loop_attr + (size_t)u * EDD; }
        float ea[6];
#pragma unroll
        for (int d = 0; d < 6; d++) ea[d] = __ldg(&ar[d]);

        float4 x0 = hlv[u * 64 + lane], x1 = hlv[u * 64 + 32 + lane];
        float xv[8] = {x0.x, x0.y, x0.z, x0.w, x1.x, x1.y, x1.z, x1.w};

        float tsum = 0.f;
#pragma unroll
        for (int q = 0; q < 8; q++) {
            float e = ea[0] * wef[0][q];
            e = fmaf(ea[1], wef[1][q], e);
            e = fmaf(ea[2], wef[2][q], e);
            e = fmaf(ea[3], wef[3][q], e);
            e = fmaf(ea[4], wef[4][q], e);
            e = fmaf(ea[5], wef[5][q], e);
            float m = xv[q] + hv[q] + e;
            m = (m > 0.f) ? m : NEGS * m;
            tsum = fmaf(m, av[q], tsum);
        }
#pragma unroll
        for (int o = 16; o > 0; o >>= 1) tsum += __shfl_xor_sync(0xffffffffu, tsum, o);

        // online softmax update
        float nm = fmaxf(mx, tsum);
        float cor = __expf(mx - nm);
        float w = __expf(tsum - nm);
        ssum = ssum * cor + w;
#pragma unroll
        for (int q = 0; q < 8; q++) acc[q] = fmaf(acc[q], cor, w * xv[q]);
        mx = nm;
    }

    float inv = 1.f / ssum;
    const float4* bv4 = (const float4*)bias;
    float4 b0 = bv4[lane], b1 = bv4[32 + lane];
    float bv[8] = {b0.x, b0.y, b0.z, b0.w, b1.x, b1.y, b1.z, b1.w};
    float ov[8];
#pragma unroll
    for (int q = 0; q < 8; q++) ov[q] = fmaf(acc[q], inv, bv[q]);

    float msum = 0.f;
#pragma unroll
    for (int q = 0; q < 8; q++) msum += ov[q];
#pragma unroll
    for (int o = 16; o > 0; o >>= 1) msum += __shfl_xor_sync(0xffffffffu, msum, o);
    float mu = msum * (1.f / 256.f);

    float vs = 0.f;
#pragma unroll
    for (int q = 0; q < 8; q++) { float dl = ov[q] - mu; vs = fmaf(dl, dl, vs); }
#pragma unroll
    for (int o = 16; o > 0; o >>= 1) vs += __shfl_xor_sync(0xffffffffu, vs, o);
    float rstd = rsqrtf(vs * (1.f / 256.f) + EPSL);

    const float4* lw4 = (const float4*)lnw;
    const float4* lb4 = (const float4*)lnb;
    float4 lw0 = lw4[lane], lw1 = lw4[32 + lane];
    float4 lb0 = lb4[lane], lb1 = lb4[32 + lane];
    float lwv[8] = {lw0.x, lw0.y, lw0.z, lw0.w, lw1.x, lw1.y, lw1.z, lw1.w};
    float lbv[8] = {lb0.x, lb0.y, lb0.z, lb0.w, lb1.x, lb1.y, lb1.z, lb1.w};

    float yv[8];
#pragma unroll
    for (int q = 0; q < 8; q++) {
        float y = fmaf((ov[q] - mu) * rstd, lwv[q], lbv[q]);
        yv[q] = fmaxf(y, 0.f);
    }
    float4* hov = (float4*)g_h;
    hov[n * 64 + lane] = make_float4(yv[0], yv[1], yv[2], yv[3]);
    hov[n * 64 + 32 + lane] = make_float4(yv[4], yv[5], yv[6], yv[7]);
}

// ---------------- pooling + final projection ----------------
__global__ void k_pool() {
    int g = blockIdx.x, t = threadIdx.x;
    int s = g_gstart[g], e = g_gstart[g + 1];
    float acc = 0.f;
    for (int n = s; n < e; n++) acc += g_h[(size_t)n * Hh + t];
    int c = e - s;
    g_pool[g * Hh + t] = acc / (float)(c > 1 ? c : 1);
}

__global__ void k_final(const float* __restrict__ linW, const float* __restrict__ linb,
                        float* __restrict__ out) {
    __shared__ float row[Hh];
    int g = blockIdx.x, t = threadIdx.x;
    row[t] = g_pool[g * Hh + t];
    __syncthreads();
    float acc = linb[t];
#pragma unroll 8
    for (int k = 0; k < Hh; k++) acc = fmaf(row[k], linW[(size_t)k * Hh + t], acc);
    out[g * Hh + t] = acc;
}

// ---------------- launch ----------------
extern "C" void kernel_launch(void* const* d_in, const int* in_sizes, int n_in,
                              void* d_out, int out_size) {
    const float* x     = (const float*)d_in[0];
    const int*   ei    = (const int*)d_in[1];
    const int*   src   = ei;
    const int*   dst   = ei + Ee;
    const float* eattr = (const float*)d_in[2];
    const int*   batch = (const int*)d_in[3];
    const float* Wl0   = (const float*)d_in[4];
    const float* Wr0   = (const float*)d_in[5];
    const float* Wl    = (const float*)d_in[6];
    const float* Wr    = (const float*)d_in[7];
    const float* bl    = (const float*)d_in[8];
    const float* br    = (const float*)d_in[9];
    const float* We    = (const float*)d_in[10];
    const float* att   = (const float*)d_in[11];
    const float* bias  = (const float*)d_in[12];
    const float* lnw   = (const float*)d_in[13];
    const float* lnb   = (const float*)d_in[14];
    const float* linW  = (const float*)d_in[15];
    const float* linb  = (const float*)d_in[16];
    float* out = (float*)d_out;

    float* h_ptr = nullptr;
    cudaGetSymbolAddress((void**)&h_ptr, g_h);

    k_init<<<128, 256>>>();
    k_hist<<<(Ee + 255) / 256, 256>>>(dst, eattr);
    k_nodeprep<<<(Nn + 255) / 256, 256>>>(batch);
    k_scan<<<1, 1024>>>();
    k_gstart<<<1, 32>>>();
    k_scatter<<<(EP + 255) / 256, 256>>>(dst);

    for (int l = 0; l < 4; l++) {
        const float* Aptr = (l == 0) ? x : (const float*)h_ptr;
        int K = (l == 0) ? IND : Hh;
        const float* wl = (l == 0) ? Wl0 : Wl + (size_t)(l - 1) * Hh * Hh;
        const float* wr = (l == 0) ? Wr0 : Wr + (size_t)(l - 1) * Hh * Hh;
        dim3 gg((Nn + 127) / 128, 4);
        k_gemm<<<gg, 256>>>(Aptr, K, wl, wr, bl + l * Hh, br + l * Hh);
        k_edge<<<(Nn + 7) / 8, 256>>>(src, eattr, We + (size_t)l * EDD * Hh,
                                      att + l * Hh, bias + l * Hh,
                                      lnw + l * Hh, lnb + l * Hh);
    }

    k_pool<<<Gg, 256>>>();
    k_final<<<Gg, 256>>>(linW, linb, out);
}

// round 2
// speedup vs baseline: 1.5113x; 1.5113x over previous
#include <cuda_runtime.h>
#include <math.h>

#define Nn 20000
#define Ee 320000
#define EP (Ee + Nn)
#define Gg 64
#define IND 23
#define EDD 6
#define Hh 256
#define NEGS 0.2f
#define EPSL 1e-5f

// ---------------- scratch (device globals; no allocation allowed) ----------------
__device__ __align__(16) float g_hl[Nn * Hh];
__device__ __align__(16) float g_hr[Nn * Hh];
__device__ __align__(16) float g_h[Nn * Hh];
__device__ float g_loop_attr[Nn * EDD];
__device__ int g_deg[Nn];
__device__ int g_rowptr[Nn + 1];
__device__ int g_fill[Nn];
__device__ int g_eid[EP];
__device__ int g_gcnt[Gg];
__device__ int g_gstart[Gg + 1];
__device__ __align__(16) float g_pool[Gg * Hh];

// ---------------- setup kernels ----------------
__global__ void k_init() {
    int i = blockIdx.x * blockDim.x + threadIdx.x;
    int stride = gridDim.x * blockDim.x;
    for (int n = i; n < Nn; n += stride) { g_deg[n] = 0; g_fill[n] = 0; }
    for (int n = i; n < Nn * EDD; n += stride) g_loop_attr[n] = 0.f;
    if (i < Gg) g_gcnt[i] = 0;
}

__global__ void k_hist(const int* __restrict__ dst, const float* __restrict__ eattr) {
    int e = blockIdx.x * blockDim.x + threadIdx.x;
    if (e >= Ee) return;
    int d = dst[e];
    atomicAdd(&g_deg[d], 1);
#pragma unroll
    for (int t = 0; t < EDD; t++) atomicAdd(&g_loop_attr[d * EDD + t], eattr[e * EDD + t]);
}

__global__ void k_nodeprep(const int* __restrict__ batch) {
    int n = blockIdx.x * blockDim.x + threadIdx.x;
    if (n >= Nn) return;
    int dg = g_deg[n];
    float inv = 1.f / (float)(dg > 1 ? dg : 1);
#pragma unroll
    for (int t = 0; t < EDD; t++) g_loop_attr[n * EDD + t] *= inv;
    atomicAdd(&g_gcnt[batch[n]], 1);
}

// Parallel scan: 1024 threads x 20 elements each (covers 20480 >= Nn)
__global__ __launch_bounds__(1024) void k_scan2() {
    __shared__ int wsum[32];
    const int CH = 20;
    int t = threadIdx.x;
    int lane = t & 31, w = t >> 5;
    int base = t * CH;
    int local[CH];
    int s = 0;
#pragma unroll
    for (int i = 0; i < CH; i++) {
        int idx = base + i;
        int v = (idx < Nn) ? (g_deg[idx] + 1) : 0;
        local[i] = s;
        s += v;
    }
    // inclusive warp scan of s
    int ws = s;
#pragma unroll
    for (int o = 1; o < 32; o <<= 1) {
        int u = __shfl_up_sync(0xffffffffu, ws, o);
        if (lane >= o) ws += u;
    }
    if (lane == 31) wsum[w] = ws;
    __syncthreads();
    if (w == 0) {
        int v = wsum[lane];
        int iv = v;
#pragma unroll
        for (int o = 1; o < 32; o <<= 1) {
            int u = __shfl_up_sync(0xffffffffu, iv, o);
            if (lane >= o) iv += u;
        }
        wsum[lane] = iv - v;  // exclusive warp offsets
    }
    __syncthreads();
    int off = wsum[w] + (ws - s);
#pragma unroll
    for (int i = 0; i < CH; i++) {
        int idx = base + i;
        if (idx < Nn) g_rowptr[idx] = off + local[i];
    }
    if (t == 1023) g_rowptr[Nn] = off + s;
}

__global__ void k_gstart() {
    if (threadIdx.x == 0 && blockIdx.x == 0) {
        int acc = 0;
        for (int g = 0; g < Gg; g++) { g_gstart[g] = acc; acc += g_gcnt[g]; }
        g_gstart[Gg] = acc;
    }
}

__global__ void k_scatter(const int* __restrict__ dst) {
    int e = blockIdx.x * blockDim.x + threadIdx.x;
    if (e >= EP) return;
    int d = (e < Ee) ? dst[e] : (e - Ee);
    int slot = g_rowptr[d] + atomicAdd(&g_fill[d], 1);
    g_eid[slot] = e;
}

// ---------------- SIMT GEMM (layer 0 only, K=23) ----------------
__global__ __launch_bounds__(256) void k_gemm(const float* __restrict__ A, int K,
                                              const float* __restrict__ Wl,
                                              const float* __restrict__ Wr,
                                              const float* __restrict__ bl,
                                              const float* __restrict__ br) {
    __shared__ float As[16][128];
    __shared__ float Bs[16][128];
    int t = threadIdx.x;
    int m0 = blockIdx.x * 128;
    int halfsel = blockIdx.y >> 1;
    int cb = (blockIdx.y & 1) * 128;
    const float* W = halfsel ? Wr : Wl;
    const float* bias = halfsel ? br : bl;
    float* outp = halfsel ? g_hr : g_hl;
    int ty = t >> 4, tx = t & 15;
    float acc[8][8];
#pragma unroll
    for (int i = 0; i < 8; i++)
#pragma unroll
        for (int j = 0; j < 8; j++) acc[i][j] = 0.f;

    for (int k0 = 0; k0 < K; k0 += 16) {
#pragma unroll
        for (int i = 0; i < 8; i++) {
            int lin = t + 256 * i;
            int k = lin & 15, m = lin >> 4;
            int row = m0 + m, kk = k0 + k;
            As[k][m] = (row < Nn && kk < K) ? A[(size_t)row * K + kk] : 0.f;
        }
#pragma unroll
        for (int i = 0; i < 8; i++) {
            int lin = t + 256 * i;
            int nn = lin & 127, k = lin >> 7;
            int kk = k0 + k;
            Bs[k][nn] = (kk < K) ? W[(size_t)kk * Hh + cb + nn] : 0.f;
        }
        __syncthreads();
#pragma unroll
        for (int k = 0; k < 16; k++) {
            float a[8], b[8];
#pragma unroll
            for (int i = 0; i < 8; i++) { a[i] = As[k][ty * 8 + i]; b[i] = Bs[k][tx * 8 + i]; }
#pragma unroll
            for (int i = 0; i < 8; i++)
#pragma unroll
                for (int j = 0; j < 8; j++) acc[i][j] = fmaf(a[i], b[j], acc[i][j]);
        }
        __syncthreads();
    }
#pragma unroll
    for (int i = 0; i < 8; i++) {
        int row = m0 + ty * 8 + i;
        if (row >= Nn) continue;
#pragma unroll
        for (int j = 0; j < 8; j++) {
            int col = cb + tx * 8 + j;
            outp[(size_t)row * Hh + col] = acc[i][j] + bias[col];
        }
    }
}

// ---------------- Tensor-core GEMM (K=256 layers) ----------------
// tf32 mma with exact-split compensation: hi = trunc_tf32(a), lo = a - hi,
// D += hi_a*hi_b + lo_a*hi_b + hi_a*lo_b  (error ~2^-21)
__device__ __forceinline__ void tsplit(float a, unsigned& hi, unsigned& lo) {
    unsigned ai = __float_as_uint(a);
    hi = ai & 0xFFFFE000u;
    lo = __float_as_uint(a - __uint_as_float(hi));
}

__device__ __forceinline__ void mma_tf32(float c[4], unsigned a0, unsigned a1,
                                         unsigned a2, unsigned a3,
                                         unsigned b0, unsigned b1) {
    asm volatile(
        "mma.sync.aligned.m16n8k8.row.col.f32.tf32.tf32.f32 "
        "{%0,%1,%2,%3}, {%4,%5,%6,%7}, {%8,%9}, {%0,%1,%2,%3};"
        : "+f"(c[0]), "+f"(c[1]), "+f"(c[2]), "+f"(c[3])
        : "r"(a0), "r"(a1), "r"(a2), "r"(a3), "r"(b0), "r"(b1));
}

__global__ __launch_bounds__(256) void k_gemm_tc(const float* __restrict__ A,
                                                 const float* __restrict__ Wl,
                                                 const float* __restrict__ Wr,
                                                 const float* __restrict__ bl,
                                                 const float* __restrict__ br) {
    __shared__ float As[128][20];   // pad 20 -> fragment loads conflict-free
    __shared__ float Bs[16][136];   // pad 136 -> fragment loads conflict-free
    int t = threadIdx.x, lane = t & 31, warp = t >> 5;
    int m0 = blockIdx.x * 128;
    int halfsel = blockIdx.y >> 1;
    int cb = (blockIdx.y & 1) * 128;
    const float* W = halfsel ? Wr : Wl;
    const float* bias = halfsel ? br : bl;
    float* outp = halfsel ? g_hr : g_hl;
    int wm = (warp >> 2) * 64;  // warp row (2 rows of 64)
    int wn = (warp & 3) * 32;   // warp col (4 cols of 32)

    float c[4][4][4];
#pragma unroll
    for (int mi = 0; mi < 4; mi++)
#pragma unroll
        for (int ni = 0; ni < 4; ni++)
#pragma unroll
            for (int q = 0; q < 4; q++) c[mi][ni][q] = 0.f;

    // A load: 512 float4 (128 rows x 4); B load: 512 float4 (16 rows x 32)
    int aidx0 = t, aidx1 = t + 256;
    int arow0 = aidx0 >> 2, ac40 = aidx0 & 3;
    int arow1 = aidx1 >> 2, ac41 = aidx1 & 3;
    int gr0 = m0 + arow0; gr0 = gr0 < Nn ? gr0 : Nn - 1;
    int gr1 = m0 + arow1; gr1 = gr1 < Nn ? gr1 : Nn - 1;
    int brow0 = aidx0 >> 5, bc40 = aidx0 & 31;
    int brow1 = aidx1 >> 5, bc41 = aidx1 & 31;

    float4 ra0, ra1, rb0, rb1;
    ra0 = *(const float4*)&A[(size_t)gr0 * Hh + ac40 * 4];
    ra1 = *(const float4*)&A[(size_t)gr1 * Hh + ac41 * 4];
    rb0 = *(const float4*)&W[(size_t)brow0 * Hh + cb + bc40 * 4];
    rb1 = *(const float4*)&W[(size_t)brow1 * Hh + cb + bc41 * 4];
    *(float4*)&As[arow0][ac40 * 4] = ra0;
    *(float4*)&As[arow1][ac41 * 4] = ra1;
    *(float4*)&Bs[brow0][bc40 * 4] = rb0;
    *(float4*)&Bs[brow1][bc41 * 4] = rb1;
    __syncthreads();

    int g = lane >> 2, tg = lane & 3;

    for (int k0 = 0; k0 < Hh; k0 += 16) {
        bool hasnext = (k0 + 16) < Hh;
        if (hasnext) {
            int kn = k0 + 16;
            ra0 = *(const float4*)&A[(size_t)gr0 * Hh + kn + ac40 * 4];
            ra1 = *(const float4*)&A[(size_t)gr1 * Hh + kn + ac41 * 4];
            rb0 = *(const float4*)&W[(size_t)(kn + brow0) * Hh + cb + bc40 * 4];
            rb1 = *(const float4*)&W[(size_t)(kn + brow1) * Hh + cb + bc41 * 4];
        }
#pragma unroll
        for (int ks = 0; ks < 2; ks++) {
            int kk = ks * 8 + tg;
            unsigned ah[4][4], al[4][4];
#pragma unroll
            for (int mi = 0; mi < 4; mi++) {
                int r = wm + mi * 16 + g;
                tsplit(As[r][kk],       ah[mi][0], al[mi][0]);
                tsplit(As[r + 8][kk],   ah[mi][1], al[mi][1]);
                tsplit(As[r][kk + 4],   ah[mi][2], al[mi][2]);
                tsplit(As[r + 8][kk + 4], ah[mi][3], al[mi][3]);
            }
#pragma unroll
            for (int ni = 0; ni < 4; ni++) {
                int col = wn + ni * 8 + g;
                unsigned bh0, bl0, bh1, bl1;
                tsplit(Bs[kk][col],     bh0, bl0);
                tsplit(Bs[kk + 4][col], bh1, bl1);
#pragma unroll
                for (int mi = 0; mi < 4; mi++) {
                    mma_tf32(c[mi][ni], ah[mi][0], ah[mi][1], ah[mi][2], ah[mi][3], bh0, bh1);
                    mma_tf32(c[mi][ni], al[mi][0], al[mi][1], al[mi][2], al[mi][3], bh0, bh1);
                    mma_tf32(c[mi][ni], ah[mi][0], ah[mi][1], ah[mi][2], ah[mi][3], bl0, bl1);
                }
            }
        }
        __syncthreads();
        if (hasnext) {
            *(float4*)&As[arow0][ac40 * 4] = ra0;
            *(float4*)&As[arow1][ac41 * 4] = ra1;
            *(float4*)&Bs[brow0][bc40 * 4] = rb0;
            *(float4*)&Bs[brow1][bc41 * 4] = rb1;
            __syncthreads();
        }
    }

    // epilogue
#pragma unroll
    for (int mi = 0; mi < 4; mi++) {
        int row = m0 + wm + mi * 16 + g;
#pragma unroll
        for (int ni = 0; ni < 4; ni++) {
            int colb = cb + wn + ni * 8 + 2 * tg;
            float b0 = bias[colb], b1 = bias[colb + 1];
            if (row < Nn) {
                float2 v = make_float2(c[mi][ni][0] + b0, c[mi][ni][1] + b1);
                *(float2*)&outp[(size_t)row * Hh + colb] = v;
            }
            if (row + 8 < Nn) {
                float2 v = make_float2(c[mi][ni][2] + b0, c[mi][ni][3] + b1);
                *(float2*)&outp[(size_t)(row + 8) * Hh + colb] = v;
            }
        }
    }
}

// ---------------- Fused edge kernel: one warp per node ----------------
__global__ __launch_bounds__(256) void k_edge(const int* __restrict__ srcArr,
                                              const float* __restrict__ eattr,
                                              const float* __restrict__ We,
                                              const float* __restrict__ att,
                                              const float* __restrict__ bias,
                                              const float* __restrict__ lnw,
                                              const float* __restrict__ lnb) {
    int warp = threadIdx.x >> 5, lane = threadIdx.x & 31;
    int n = blockIdx.x * 8 + warp;
    if (n >= Nn) return;

    const float4* hlv = (const float4*)g_hl;
    const float4* hrv = (const float4*)g_hr;

    float4 h0 = hrv[n * 64 + lane], h1 = hrv[n * 64 + 32 + lane];
    float hv[8] = {h0.x, h0.y, h0.z, h0.w, h1.x, h1.y, h1.z, h1.w};
    const float4* attv = (const float4*)att;
    float4 a0 = attv[lane], a1 = attv[32 + lane];
    float av[8] = {a0.x, a0.y, a0.z, a0.w, a1.x, a1.y, a1.z, a1.w};

    float wef[6][8];
    const float4* Wev = (const float4*)We;
#pragma unroll
    for (int d = 0; d < 6; d++) {
        float4 w0 = Wev[d * 64 + lane], w1 = Wev[d * 64 + 32 + lane];
        wef[d][0] = w0.x; wef[d][1] = w0.y; wef[d][2] = w0.z; wef[d][3] = w0.w;
        wef[d][4] = w1.x; wef[d][5] = w1.y; wef[d][6] = w1.z; wef[d][7] = w1.w;
    }

    int r0 = g_rowptr[n], r1 = g_rowptr[n + 1];
    float mx = -3.4e38f;
    float ssum = 0.f;
    float acc[8] = {0.f, 0.f, 0.f, 0.f, 0.f, 0.f, 0.f, 0.f};

    for (int s = r0; s < r1; s++) {
        int eid = g_eid[s];
        int u;
        const float* ar;
        if (eid < Ee) { u = srcArr[eid]; ar = eattr + (size_t)eid * EDD; }
        else          { u = eid - Ee;    ar = g_loop_attr + (size_t)u * EDD; }
        float ea[6];
#pragma unroll
        for (int d = 0; d < 6; d++) ea[d] = __ldg(&ar[d]);

        float4 x0 = hlv[u * 64 + lane], x1 = hlv[u * 64 + 32 + lane];
        float xv[8] = {x0.x, x0.y, x0.z, x0.w, x1.x, x1.y, x1.z, x1.w};

        float tsum = 0.f;
#pragma unroll
        for (int q = 0; q < 8; q++) {
            float e = ea[0] * wef[0][q];
            e = fmaf(ea[1], wef[1][q], e);
            e = fmaf(ea[2], wef[2][q], e);
            e = fmaf(ea[3], wef[3][q], e);
            e = fmaf(ea[4], wef[4][q], e);
            e = fmaf(ea[5], wef[5][q], e);
            float m = xv[q] + hv[q] + e;
            m = (m > 0.f) ? m : NEGS * m;
            tsum = fmaf(m, av[q], tsum);
        }
#pragma unroll
        for (int o = 16; o > 0; o >>= 1) tsum += __shfl_xor_sync(0xffffffffu, tsum, o);

        float nm = fmaxf(mx, tsum);
        float cor = __expf(mx - nm);
        float w = __expf(tsum - nm);
        ssum = ssum * cor + w;
#pragma unroll
        for (int q = 0; q < 8; q++) acc[q] = fmaf(acc[q], cor, w * xv[q]);
        mx = nm;
    }

    float inv = 1.f / ssum;
    const float4* bv4 = (const float4*)bias;
    float4 b0 = bv4[lane], b1 = bv4[32 + lane];
    float bv[8] = {b0.x, b0.y, b0.z, b0.w, b1.x, b1.y, b1.z, b1.w};
    float ov[8];
#pragma unroll
    for (int q = 0; q < 8; q++) ov[q] = fmaf(acc[q], inv, bv[q]);

    float msum = 0.f;
#pragma unroll
    for (int q = 0; q < 8; q++) msum += ov[q];
#pragma unroll
    for (int o = 16; o > 0; o >>= 1) msum += __shfl_xor_sync(0xffffffffu, msum, o);
    float mu = msum * (1.f / 256.f);

    float vs = 0.f;
#pragma unroll
    for (int q = 0; q < 8; q++) { float dl = ov[q] - mu; vs = fmaf(dl, dl, vs); }
#pragma unroll
    for (int o = 16; o > 0; o >>= 1) vs += __shfl_xor_sync(0xffffffffu, vs, o);
    float rstd = rsqrtf(vs * (1.f / 256.f) + EPSL);

    const float4* lw4 = (const float4*)lnw;
    const float4* lb4 = (const float4*)lnb;
    float4 lw0 = lw4[lane], lw1 = lw4[32 + lane];
    float4 lb0 = lb4[lane], lb1 = lb4[32 + lane];
    float lwv[8] = {lw0.x, lw0.y, lw0.z, lw0.w, lw1.x, lw1.y, lw1.z, lw1.w};
    float lbv[8] = {lb0.x, lb0.y, lb0.z, lb0.w, lb1.x, lb1.y, lb1.z, lb1.w};

    float yv[8];
#pragma unroll
    for (int q = 0; q < 8; q++) {
        float y = fmaf((ov[q] - mu) * rstd, lwv[q], lbv[q]);
        yv[q] = fmaxf(y, 0.f);
    }
    float4* hov = (float4*)g_h;
    hov[n * 64 + lane] = make_float4(yv[0], yv[1], yv[2], yv[3]);
    hov[n * 64 + 32 + lane] = make_float4(yv[4], yv[5], yv[6], yv[7]);
}

// ---------------- pooling + final projection ----------------
__global__ void k_pool() {
    int g = blockIdx.x, t = threadIdx.x;
    int s = g_gstart[g], e = g_gstart[g + 1];
    float acc = 0.f;
    for (int n = s; n < e; n++) acc += g_h[(size_t)n * Hh + t];
    int c = e - s;
    g_pool[g * Hh + t] = acc / (float)(c > 1 ? c : 1);
}

__global__ void k_final(const float* __restrict__ linW, const float* __restrict__ linb,
                        float* __restrict__ out) {
    __shared__ float row[Hh];
    int g = blockIdx.x, t = threadIdx.x;
    row[t] = g_pool[g * Hh + t];
    __syncthreads();
    float acc = linb[t];
#pragma unroll 8
    for (int k = 0; k < Hh; k++) acc = fmaf(row[k], linW[(size_t)k * Hh + t], acc);
    out[g * Hh + t] = acc;
}

// ---------------- launch ----------------
extern "C" void kernel_launch(void* const* d_in, const int* in_sizes, int n_in,
                              void* d_out, int out_size) {
    const float* x     = (const float*)d_in[0];
    const int*   ei    = (const int*)d_in[1];
    const int*   src   = ei;
    const int*   dst   = ei + Ee;
    const float* eattr = (const float*)d_in[2];
    const int*   batch = (const int*)d_in[3];
    const float* Wl0   = (const float*)d_in[4];
    const float* Wr0   = (const float*)d_in[5];
    const float* Wl    = (const float*)d_in[6];
    const float* Wr    = (const float*)d_in[7];
    const float* bl    = (const float*)d_in[8];
    const float* br    = (const float*)d_in[9];
    const float* We    = (const float*)d_in[10];
    const float* att   = (const float*)d_in[11];
    const float* bias  = (const float*)d_in[12];
    const float* lnw   = (const float*)d_in[13];
    const float* lnb   = (const float*)d_in[14];
    const float* linW  = (const float*)d_in[15];
    const float* linb  = (const float*)d_in[16];
    float* out = (float*)d_out;

    float* h_ptr = nullptr;
    cudaGetSymbolAddress((void**)&h_ptr, g_h);

    k_init<<<128, 256>>>();
    k_hist<<<(Ee + 255) / 256, 256>>>(dst, eattr);
    k_nodeprep<<<(Nn + 255) / 256, 256>>>(batch);
    k_scan2<<<1, 1024>>>();
    k_gstart<<<1, 32>>>();
    k_scatter<<<(EP + 255) / 256, 256>>>(dst);

    for (int l = 0; l < 4; l++) {
        dim3 gg((Nn + 127) / 128, 4);
        if (l == 0) {
            k_gemm<<<gg, 256>>>(x, IND, Wl0, Wr0, bl, br);
        } else {
            const float* wl = Wl + (size_t)(l - 1) * Hh * Hh;
            const float* wr = Wr + (size_t)(l - 1) * Hh * Hh;
            k_gemm_tc<<<gg, 256>>>((const float*)h_ptr, wl, wr, bl + l * Hh, br + l * Hh);
        }
        k_edge<<<(Nn + 7) / 8, 256>>>(src, eattr, We + (size_t)l * EDD * Hh,
                                      att + l * Hh, bias + l * Hh,
                                      lnw + l * Hh, lnb + l * Hh);
    }

    k_pool<<<Gg, 256>>>();
    k_final<<<Gg, 256>>>(linW, linb, out);
}

// round 3
// speedup vs baseline: 1.9306x; 1.2774x over previous
#include <cuda_runtime.h>
#include <math.h>

#define Nn 20000
#define Ee 320000
#define Gg 64
#define IND 23
#define EDD 6
#define Hh 256
#define NEGS 0.2f
#define EPSL 1e-5f

// ---------------- scratch (device globals; no allocation allowed) ----------------
__device__ __align__(16) float g_hl[Nn * Hh];
__device__ __align__(16) float g_hr[Nn * Hh];
__device__ __align__(16) float g_h[Nn * Hh];
__device__ int g_deg[Nn];
__device__ int g_rowptr[Nn + 1];
__device__ int g_fill[Nn];
__device__ int g_eid[Ee];
__device__ int g_gstart[Gg + 1];
__device__ __align__(16) float g_pool[Gg * Hh];

// ---------------- setup kernels ----------------
__global__ void k_init(const int* __restrict__ batch) {
    int i = blockIdx.x * blockDim.x + threadIdx.x;
    int stride = gridDim.x * blockDim.x;
    for (int n = i; n < Nn; n += stride) { g_deg[n] = 0; g_fill[n] = 0; }
    for (int n = i; n < Gg * Hh; n += stride) g_pool[n] = 0.f;
    if (i <= Gg) {
        int lo = 0, hi = Nn;
        while (lo < hi) {
            int mid = (lo + hi) >> 1;
            if (batch[mid] < i) lo = mid + 1; else hi = mid;
        }
        g_gstart[i] = lo;
    }
}

__global__ void k_hist(const int* __restrict__ dst) {
    int e = blockIdx.x * blockDim.x + threadIdx.x;
    if (e < Ee) atomicAdd(&g_deg[dst[e]], 1);
}

// Parallel scan: 1024 threads x 20 elements each (covers 20480 >= Nn)
__global__ __launch_bounds__(1024) void k_scan2() {
    __shared__ int wsum[32];
    const int CH = 20;
    int t = threadIdx.x;
    int lane = t & 31, w = t >> 5;
    int base = t * CH;
    int local[CH];
    int s = 0;
#pragma unroll
    for (int i = 0; i < CH; i++) {
        int idx = base + i;
        int v = (idx < Nn) ? g_deg[idx] : 0;
        local[i] = s;
        s += v;
    }
    int ws = s;
#pragma unroll
    for (int o = 1; o < 32; o <<= 1) {
        int u = __shfl_up_sync(0xffffffffu, ws, o);
        if (lane >= o) ws += u;
    }
    if (lane == 31) wsum[w] = ws;
    __syncthreads();
    if (w == 0) {
        int v = wsum[lane];
        int iv = v;
#pragma unroll
        for (int o = 1; o < 32; o <<= 1) {
            int u = __shfl_up_sync(0xffffffffu, iv, o);
            if (lane >= o) iv += u;
        }
        wsum[lane] = iv - v;
    }
    __syncthreads();
    int off = wsum[w] + (ws - s);
#pragma unroll
    for (int i = 0; i < CH; i++) {
        int idx = base + i;
        if (idx < Nn) g_rowptr[idx] = off + local[i];
    }
    if (t == 1023) g_rowptr[Nn] = off + s;
}

__global__ void k_scatter(const int* __restrict__ dst) {
    int e = blockIdx.x * blockDim.x + threadIdx.x;
    if (e >= Ee) return;
    int d = dst[e];
    int slot = g_rowptr[d] + atomicAdd(&g_fill[d], 1);
    g_eid[slot] = e;
}

// ---------------- SIMT GEMM (layer 0 only, K=23) ----------------
__global__ __launch_bounds__(256) void k_gemm(const float* __restrict__ A, int K,
                                              const float* __restrict__ Wl,
                                              const float* __restrict__ Wr,
                                              const float* __restrict__ bl,
                                              const float* __restrict__ br) {
    __shared__ float As[16][128];
    __shared__ float Bs[16][128];
    int t = threadIdx.x;
    int m0 = blockIdx.x * 128;
    int halfsel = blockIdx.y >> 1;
    int cb = (blockIdx.y & 1) * 128;
    const float* W = halfsel ? Wr : Wl;
    const float* bias = halfsel ? br : bl;
    float* outp = halfsel ? g_hr : g_hl;
    int ty = t >> 4, tx = t & 15;
    float acc[8][8];
#pragma unroll
    for (int i = 0; i < 8; i++)
#pragma unroll
        for (int j = 0; j < 8; j++) acc[i][j] = 0.f;

    for (int k0 = 0; k0 < K; k0 += 16) {
#pragma unroll
        for (int i = 0; i < 8; i++) {
            int lin = t + 256 * i;
            int k = lin & 15, m = lin >> 4;
            int row = m0 + m, kk = k0 + k;
            As[k][m] = (row < Nn && kk < K) ? A[(size_t)row * K + kk] : 0.f;
        }
#pragma unroll
        for (int i = 0; i < 8; i++) {
            int lin = t + 256 * i;
            int nn = lin & 127, k = lin >> 7;
            int kk = k0 + k;
            Bs[k][nn] = (kk < K) ? W[(size_t)kk * Hh + cb + nn] : 0.f;
        }
        __syncthreads();
#pragma unroll
        for (int k = 0; k < 16; k++) {
            float a[8], b[8];
#pragma unroll
            for (int i = 0; i < 8; i++) { a[i] = As[k][ty * 8 + i]; b[i] = Bs[k][tx * 8 + i]; }
#pragma unroll
            for (int i = 0; i < 8; i++)
#pragma unroll
                for (int j = 0; j < 8; j++) acc[i][j] = fmaf(a[i], b[j], acc[i][j]);
        }
        __syncthreads();
    }
#pragma unroll
    for (int i = 0; i < 8; i++) {
        int row = m0 + ty * 8 + i;
        if (row >= Nn) continue;
#pragma unroll
        for (int j = 0; j < 8; j++) {
            int col = cb + tx * 8 + j;
            outp[(size_t)row * Hh + col] = acc[i][j] + bias[col];
        }
    }
}

// ---------------- Tensor-core GEMM (K=256 layers) ----------------
__device__ __forceinline__ void tsplit(float a, unsigned& hi, unsigned& lo) {
    unsigned ai = __float_as_uint(a);
    hi = ai & 0xFFFFE000u;
    lo = __float_as_uint(a - __uint_as_float(hi));
}

__device__ __forceinline__ void mma_tf32(float c[4], unsigned a0, unsigned a1,
                                         unsigned a2, unsigned a3,
                                         unsigned b0, unsigned b1) {
    asm volatile(
        "mma.sync.aligned.m16n8k8.row.col.f32.tf32.tf32.f32 "
        "{%0,%1,%2,%3}, {%4,%5,%6,%7}, {%8,%9}, {%0,%1,%2,%3};"
        : "+f"(c[0]), "+f"(c[1]), "+f"(c[2]), "+f"(c[3])
        : "r"(a0), "r"(a1), "r"(a2), "r"(a3), "r"(b0), "r"(b1));
}

__global__ __launch_bounds__(256) void k_gemm_tc(const float* __restrict__ A,
                                                 const float* __restrict__ Wl,
                                                 const float* __restrict__ Wr,
                                                 const float* __restrict__ bl,
                                                 const float* __restrict__ br) {
    __shared__ float As[128][20];
    __shared__ float Bs[16][136];
    int t = threadIdx.x, lane = t & 31, warp = t >> 5;
    int m0 = blockIdx.x * 128;
    int halfsel = blockIdx.y >> 1;
    int cb = (blockIdx.y & 1) * 128;
    const float* W = halfsel ? Wr : Wl;
    const float* bias = halfsel ? br : bl;
    float* outp = halfsel ? g_hr : g_hl;
    int wm = (warp >> 2) * 64;
    int wn = (warp & 3) * 32;

    float c[4][4][4];
#pragma unroll
    for (int mi = 0; mi < 4; mi++)
#pragma unroll
        for (int ni = 0; ni < 4; ni++)
#pragma unroll
            for (int q = 0; q < 4; q++) c[mi][ni][q] = 0.f;

    int aidx0 = t, aidx1 = t + 256;
    int arow0 = aidx0 >> 2, ac40 = aidx0 & 3;
    int arow1 = aidx1 >> 2, ac41 = aidx1 & 3;
    int gr0 = m0 + arow0; gr0 = gr0 < Nn ? gr0 : Nn - 1;
    int gr1 = m0 + arow1; gr1 = gr1 < Nn ? gr1 : Nn - 1;
    int brow0 = aidx0 >> 5, bc40 = aidx0 & 31;
    int brow1 = aidx1 >> 5, bc41 = aidx1 & 31;

    float4 ra0, ra1, rb0, rb1;
    ra0 = *(const float4*)&A[(size_t)gr0 * Hh + ac40 * 4];
    ra1 = *(const float4*)&A[(size_t)gr1 * Hh + ac41 * 4];
    rb0 = *(const float4*)&W[(size_t)brow0 * Hh + cb + bc40 * 4];
    rb1 = *(const float4*)&W[(size_t)brow1 * Hh + cb + bc41 * 4];
    *(float4*)&As[arow0][ac40 * 4] = ra0;
    *(float4*)&As[arow1][ac41 * 4] = ra1;
    *(float4*)&Bs[brow0][bc40 * 4] = rb0;
    *(float4*)&Bs[brow1][bc41 * 4] = rb1;
    __syncthreads();

    int g = lane >> 2, tg = lane & 3;

    for (int k0 = 0; k0 < Hh; k0 += 16) {
        bool hasnext = (k0 + 16) < Hh;
        if (hasnext) {
            int kn = k0 + 16;
            ra0 = *(const float4*)&A[(size_t)gr0 * Hh + kn + ac40 * 4];
            ra1 = *(const float4*)&A[(size_t)gr1 * Hh + kn + ac41 * 4];
            rb0 = *(const float4*)&W[(size_t)(kn + brow0) * Hh + cb + bc40 * 4];
            rb1 = *(const float4*)&W[(size_t)(kn + brow1) * Hh + cb + bc41 * 4];
        }
#pragma unroll
        for (int ks = 0; ks < 2; ks++) {
            int kk = ks * 8 + tg;
            unsigned ah[4][4], al[4][4];
#pragma unroll
            for (int mi = 0; mi < 4; mi++) {
                int r = wm + mi * 16 + g;
                tsplit(As[r][kk],         ah[mi][0], al[mi][0]);
                tsplit(As[r + 8][kk],     ah[mi][1], al[mi][1]);
                tsplit(As[r][kk + 4],     ah[mi][2], al[mi][2]);
                tsplit(As[r + 8][kk + 4], ah[mi][3], al[mi][3]);
            }
#pragma unroll
            for (int ni = 0; ni < 4; ni++) {
                int col = wn + ni * 8 + g;
                unsigned bh0, bl0, bh1, bl1;
                tsplit(Bs[kk][col],     bh0, bl0);
                tsplit(Bs[kk + 4][col], bh1, bl1);
#pragma unroll
                for (int mi = 0; mi < 4; mi++) {
                    mma_tf32(c[mi][ni], ah[mi][0], ah[mi][1], ah[mi][2], ah[mi][3], bh0, bh1);
                    mma_tf32(c[mi][ni], al[mi][0], al[mi][1], al[mi][2], al[mi][3], bh0, bh1);
                    mma_tf32(c[mi][ni], ah[mi][0], ah[mi][1], ah[mi][2], ah[mi][3], bl0, bl1);
                }
            }
        }
        __syncthreads();
        if (hasnext) {
            *(float4*)&As[arow0][ac40 * 4] = ra0;
            *(float4*)&As[arow1][ac41 * 4] = ra1;
            *(float4*)&Bs[brow0][bc40 * 4] = rb0;
            *(float4*)&Bs[brow1][bc41 * 4] = rb1;
            __syncthreads();
        }
    }

#pragma unroll
    for (int mi = 0; mi < 4; mi++) {
        int row = m0 + wm + mi * 16 + g;
#pragma unroll
        for (int ni = 0; ni < 4; ni++) {
            int colb = cb + wn + ni * 8 + 2 * tg;
            float b0 = bias[colb], b1 = bias[colb + 1];
            if (row < Nn) {
                float2 v = make_float2(c[mi][ni][0] + b0, c[mi][ni][1] + b1);
                *(float2*)&outp[(size_t)row * Hh + colb] = v;
            }
            if (row + 8 < Nn) {
                float2 v = make_float2(c[mi][ni][2] + b0, c[mi][ni][3] + b1);
                *(float2*)&outp[(size_t)(row + 8) * Hh + colb] = v;
            }
        }
    }
}

// ---------------- Fused edge kernel: one warp per node, 2 edges/iter ----------------
// self-loop processed at the end with edge_attr = mean of in-edge attrs (computed inline)
__global__ __launch_bounds__(256) void k_edge(const int* __restrict__ srcArr,
                                              const float* __restrict__ eattr,
                                              const float* __restrict__ We,
                                              const float* __restrict__ att,
                                              const float* __restrict__ bias,
                                              const float* __restrict__ lnw,
                                              const float* __restrict__ lnb) {
    int warp = threadIdx.x >> 5, lane = threadIdx.x & 31;
    int n = blockIdx.x * 8 + warp;
    if (n >= Nn) return;

    const float4* hlv = (const float4*)g_hl;
    const float4* hrv = (const float4*)g_hr;

    float4 h0 = hrv[n * 64 + lane], h1 = hrv[n * 64 + 32 + lane];
    float hv[8] = {h0.x, h0.y, h0.z, h0.w, h1.x, h1.y, h1.z, h1.w};
    const float4* attv = (const float4*)att;
    float4 a0 = attv[lane], a1 = attv[32 + lane];
    float av[8] = {a0.x, a0.y, a0.z, a0.w, a1.x, a1.y, a1.z, a1.w};

    float wef[6][8];
    const float4* Wev = (const float4*)We;
#pragma unroll
    for (int d = 0; d < 6; d++) {
        float4 w0 = Wev[d * 64 + lane], w1 = Wev[d * 64 + 32 + lane];
        wef[d][0] = w0.x; wef[d][1] = w0.y; wef[d][2] = w0.z; wef[d][3] = w0.w;
        wef[d][4] = w1.x; wef[d][5] = w1.y; wef[d][6] = w1.z; wef[d][7] = w1.w;
    }

    int r0 = g_rowptr[n], r1 = g_rowptr[n + 1];
    int deg = r1 - r0;
    float mx = -3.4e38f;
    float ssum = 0.f;
    float acc[8] = {0.f, 0.f, 0.f, 0.f, 0.f, 0.f, 0.f, 0.f};
    float easum[6] = {0.f, 0.f, 0.f, 0.f, 0.f, 0.f};

    int s = r0;
    for (; s + 1 < r1; s += 2) {
        int e0 = __ldg(&g_eid[s]), e1 = __ldg(&g_eid[s + 1]);
        int u0 = __ldg(&srcArr[e0]), u1 = __ldg(&srcArr[e1]);
        float ea0[6], ea1[6];
#pragma unroll
        for (int d = 0; d < 6; d++) {
            ea0[d] = __ldg(&eattr[(size_t)e0 * EDD + d]);
            ea1[d] = __ldg(&eattr[(size_t)e1 * EDD + d]);
            easum[d] += ea0[d] + ea1[d];
        }
        float4 p0 = hlv[u0 * 64 + lane], p1 = hlv[u0 * 64 + 32 + lane];
        float4 q0 = hlv[u1 * 64 + lane], q1 = hlv[u1 * 64 + 32 + lane];
        float x0[8] = {p0.x, p0.y, p0.z, p0.w, p1.x, p1.y, p1.z, p1.w};
        float x1[8] = {q0.x, q0.y, q0.z, q0.w, q1.x, q1.y, q1.z, q1.w};

        float t0 = 0.f, t1 = 0.f;
#pragma unroll
        for (int q = 0; q < 8; q++) {
            float e = ea0[0] * wef[0][q];
            e = fmaf(ea0[1], wef[1][q], e);
            e = fmaf(ea0[2], wef[2][q], e);
            e = fmaf(ea0[3], wef[3][q], e);
            e = fmaf(ea0[4], wef[4][q], e);
            e = fmaf(ea0[5], wef[5][q], e);
            float m = x0[q] + hv[q] + e;
            m = (m > 0.f) ? m : NEGS * m;
            t0 = fmaf(m, av[q], t0);

            float f = ea1[0] * wef[0][q];
            f = fmaf(ea1[1], wef[1][q], f);
            f = fmaf(ea1[2], wef[2][q], f);
            f = fmaf(ea1[3], wef[3][q], f);
            f = fmaf(ea1[4], wef[4][q], f);
            f = fmaf(ea1[5], wef[5][q], f);
            float m2 = x1[q] + hv[q] + f;
            m2 = (m2 > 0.f) ? m2 : NEGS * m2;
            t1 = fmaf(m2, av[q], t1);
        }
#pragma unroll
        for (int o = 16; o > 0; o >>= 1) {
            t0 += __shfl_xor_sync(0xffffffffu, t0, o);
            t1 += __shfl_xor_sync(0xffffffffu, t1, o);
        }
        float nm = fmaxf(mx, fmaxf(t0, t1));
        float cor = __expf(mx - nm);
        float w0 = __expf(t0 - nm);
        float w1 = __expf(t1 - nm);
        ssum = fmaf(ssum, cor, w0 + w1);
#pragma unroll
        for (int q = 0; q < 8; q++)
            acc[q] = fmaf(acc[q], cor, fmaf(w0, x0[q], w1 * x1[q]));
        mx = nm;
    }
    if (s < r1) {
        int e0 = __ldg(&g_eid[s]);
        int u0 = __ldg(&srcArr[e0]);
        float ea0[6];
#pragma unroll
        for (int d = 0; d < 6; d++) {
            ea0[d] = __ldg(&eattr[(size_t)e0 * EDD + d]);
            easum[d] += ea0[d];
        }
        float4 p0 = hlv[u0 * 64 + lane], p1 = hlv[u0 * 64 + 32 + lane];
        float x0[8] = {p0.x, p0.y, p0.z, p0.w, p1.x, p1.y, p1.z, p1.w};
        float t0 = 0.f;
#pragma unroll
        for (int q = 0; q < 8; q++) {
            float e = ea0[0] * wef[0][q];
            e = fmaf(ea0[1], wef[1][q], e);
            e = fmaf(ea0[2], wef[2][q], e);
            e = fmaf(ea0[3], wef[3][q], e);
            e = fmaf(ea0[4], wef[4][q], e);
            e = fmaf(ea0[5], wef[5][q], e);
            float m = x0[q] + hv[q] + e;
            m = (m > 0.f) ? m : NEGS * m;
            t0 = fmaf(m, av[q], t0);
        }
#pragma unroll
        for (int o = 16; o > 0; o >>= 1) t0 += __shfl_xor_sync(0xffffffffu, t0, o);
        float nm = fmaxf(mx, t0);
        float cor = __expf(mx - nm);
        float w0 = __expf(t0 - nm);
        ssum = fmaf(ssum, cor, w0);
#pragma unroll
        for (int q = 0; q < 8; q++) acc[q] = fmaf(acc[q], cor, w0 * x0[q]);
        mx = nm;
    }
    // self-loop: src = dst = n, attr = easum / max(deg,1)
    {
        float inv = 1.f / (float)(deg > 1 ? deg : 1);
        float ea0[6];
#pragma unroll
        for (int d = 0; d < 6; d++) ea0[d] = easum[d] * inv;
        float4 p0 = hlv[n * 64 + lane], p1 = hlv[n * 64 + 32 + lane];
        float x0[8] = {p0.x, p0.y, p0.z, p0.w, p1.x, p1.y, p1.z, p1.w};
        float t0 = 0.f;
#pragma unroll
        for (int q = 0; q < 8; q++) {
            float e = ea0[0] * wef[0][q];
            e = fmaf(ea0[1], wef[1][q], e);
            e = fmaf(ea0[2], wef[2][q], e);
            e = fmaf(ea0[3], wef[3][q], e);
            e = fmaf(ea0[4], wef[4][q], e);
            e = fmaf(ea0[5], wef[5][q], e);
            float m = x0[q] + hv[q] + e;
            m = (m > 0.f) ? m : NEGS * m;
            t0 = fmaf(m, av[q], t0);
        }
#pragma unroll
        for (int o = 16; o > 0; o >>= 1) t0 += __shfl_xor_sync(0xffffffffu, t0, o);
        float nm = fmaxf(mx, t0);
        float cor = __expf(mx - nm);
        float w0 = __expf(t0 - nm);
        ssum = fmaf(ssum, cor, w0);
#pragma unroll
        for (int q = 0; q < 8; q++) acc[q] = fmaf(acc[q], cor, w0 * x0[q]);
    }

    float inv = 1.f / ssum;
    const float4* bv4 = (const float4*)bias;
    float4 b0 = bv4[lane], b1 = bv4[32 + lane];
    float bv[8] = {b0.x, b0.y, b0.z, b0.w, b1.x, b1.y, b1.z, b1.w};
    float ov[8];
#pragma unroll
    for (int q = 0; q < 8; q++) ov[q] = fmaf(acc[q], inv, bv[q]);

    float msum = 0.f;
#pragma unroll
    for (int q = 0; q < 8; q++) msum += ov[q];
#pragma unroll
    for (int o = 16; o > 0; o >>= 1) msum += __shfl_xor_sync(0xffffffffu, msum, o);
    float mu = msum * (1.f / 256.f);

    float vs = 0.f;
#pragma unroll
    for (int q = 0; q < 8; q++) { float dl = ov[q] - mu; vs = fmaf(dl, dl, vs); }
#pragma unroll
    for (int o = 16; o > 0; o >>= 1) vs += __shfl_xor_sync(0xffffffffu, vs, o);
    float rstd = rsqrtf(vs * (1.f / 256.f) + EPSL);

    const float4* lw4 = (const float4*)lnw;
    const float4* lb4 = (const float4*)lnb;
    float4 lw0 = lw4[lane], lw1 = lw4[32 + lane];
    float4 lb0 = lb4[lane], lb1 = lb4[32 + lane];
    float lwv[8] = {lw0.x, lw0.y, lw0.z, lw0.w, lw1.x, lw1.y, lw1.z, lw1.w};
    float lbv[8] = {lb0.x, lb0.y, lb0.z, lb0.w, lb1.x, lb1.y, lb1.z, lb1.w};

    float yv[8];
#pragma unroll
    for (int q = 0; q < 8; q++) {
        float y = fmaf((ov[q] - mu) * rstd, lwv[q], lbv[q]);
        yv[q] = fmaxf(y, 0.f);
    }
    float4* hov = (float4*)g_h;
    hov[n * 64 + lane] = make_float4(yv[0], yv[1], yv[2], yv[3]);
    hov[n * 64 + 32 + lane] = make_float4(yv[4], yv[5], yv[6], yv[7]);
}

// ---------------- pooling + final projection ----------------
__global__ void k_pool() {
    int g = blockIdx.x, c = blockIdx.y, t = threadIdx.x;
    int s = g_gstart[g], e = g_gstart[g + 1];
    float acc = 0.f;
    for (int n = s + c; n < e; n += 8) acc += g_h[(size_t)n * Hh + t];
    atomicAdd(&g_pool[g * Hh + t], acc);
}

__global__ void k_final(const float* __restrict__ linW, const float* __restrict__ linb,
                        float* __restrict__ out) {
    __shared__ float row[Hh];
    int g = blockIdx.x, t = threadIdx.x;
    int cnt = g_gstart[g + 1] - g_gstart[g];
    float invc = 1.f / (float)(cnt > 1 ? cnt : 1);
    row[t] = g_pool[g * Hh + t] * invc;
    __syncthreads();
    float acc = linb[t];
#pragma unroll 8
    for (int k = 0; k < Hh; k++) acc = fmaf(row[k], linW[(size_t)k * Hh + t], acc);
    out[g * Hh + t] = acc;
}

// ---------------- launch ----------------
extern "C" void kernel_launch(void* const* d_in, const int* in_sizes, int n_in,
                              void* d_out, int out_size) {
    const float* x     = (const float*)d_in[0];
    const int*   ei    = (const int*)d_in[1];
    const int*   src   = ei;
    const int*   dst   = ei + Ee;
    const float* eattr = (const float*)d_in[2];
    const int*   batch = (const int*)d_in[3];
    const float* Wl0   = (const float*)d_in[4];
    const float* Wr0   = (const float*)d_in[5];
    const float* Wl    = (const float*)d_in[6];
    const float* Wr    = (const float*)d_in[7];
    const float* bl    = (const float*)d_in[8];
    const float* br    = (const float*)d_in[9];
    const float* We    = (const float*)d_in[10];
    const float* att   = (const float*)d_in[11];
    const float* bias  = (const float*)d_in[12];
    const float* lnw   = (const float*)d_in[13];
    const float* lnb   = (const float*)d_in[14];
    const float* linW  = (const float*)d_in[15];
    const float* linb  = (const float*)d_in[16];
    float* out = (float*)d_out;

    float* h_ptr = nullptr;
    cudaGetSymbolAddress((void**)&h_ptr, g_h);

    k_init<<<128, 256>>>(batch);                    // launch 0
    k_hist<<<(Ee + 255) / 256, 256>>>(dst);         // launch 1
    k_scan2<<<1, 1024>>>();                         // launch 2
    k_scatter<<<(Ee + 255) / 256, 256>>>(dst);      // launch 3

    for (int l = 0; l < 4; l++) {
        dim3 gg((Nn + 127) / 128, 4);
        if (l == 0) {
            k_gemm<<<gg, 256>>>(x, IND, Wl0, Wr0, bl, br);     // launch 4
        } else {
            const float* wl = Wl + (size_t)(l - 1) * Hh * Hh;
            const float* wr = Wr + (size_t)(l - 1) * Hh * Hh;
            k_gemm_tc<<<gg, 256>>>((const float*)h_ptr, wl, wr, bl + l * Hh, br + l * Hh);
        }
        k_edge<<<(Nn + 7) / 8, 256>>>(src, eattr, We + (size_t)l * EDD * Hh,
                                      att + l * Hh, bias + l * Hh,
                                      lnw + l * Hh, lnb + l * Hh); // launch 5 at l=0 -> ncu target
    }

    k_pool<<<dim3(Gg, 8), 256>>>();
    k_final<<<Gg, 256>>>(linW, linb, out);
}